// round 13
// baseline (speedup 1.0000x reference)
#include <cuda_runtime.h>
#include <cuda_fp16.h>
#include <cstdint>
#include <float.h>

// ---------------------------------------------------------------------------
// Problem constants
// ---------------------------------------------------------------------------
#define N 4096
#define D 512
#define MARGIN 200.0f

// Tiling: CTA tile 128x128, 16 warps in 4(m) x 4(n), warp tile 32x32
#define BM 128
#define BN 128
#define KC 32                 // k per smem stage
#define KT (D / KC)           // 16 k-tiles
#define STAGES 3
#define PADH 40               // halfs per smem row (32 + 8 pad) -> ldmatrix conflict-free
#define NB (N / BM)           // 32 blocks per dim
#define NJT NB
#define NTILES (NB * (NB + 1) / 2)          // 528 upper-triangle tiles

#define STG_H (128 * PADH * 2)              // 10240 B per matrix per stage
#define OFF_A(s)  ((s) * STG_H)                       // 3 stages A
#define OFF_B(s)  (STAGES * STG_H + (s) * STG_H)      // 3 stages B
#define OFF_REDP  (2 * STAGES * STG_H)                // 61440: [128][4] floats
#define OFF_REDN  (OFF_REDP + 2048)
#define OFF_CP    (OFF_REDN + 2048)                   // [4][128] floats
#define OFF_CN    (OFF_CP + 2048)
#define OFF_JSQ   (OFF_CN + 2048)
#define OFF_JLBL  (OFF_JSQ + 512)
#define SMEM_TOTAL (OFF_JLBL + 512)                   // 70656 bytes -> 2 CTAs/SM

// ---------------------------------------------------------------------------
// Device scratch (static module storage; no runtime allocation)
// ---------------------------------------------------------------------------
__device__ __half    g_Xh[N * D];   // fp16 copy of X (4 MB)
__device__ float     g_sq[N];
__device__ int       g_lbl[N];
__device__ float     g_pos[NJT * N];
__device__ float     g_neg[NJT * N];
__device__ unsigned  g_done;        // last-CTA counter (zeroed by prep each call)

// ---------------------------------------------------------------------------
// PTX helpers (sm_80 features only — compiles for plain sm_100 target)
// ---------------------------------------------------------------------------
__device__ __forceinline__ uint32_t smem_u32(const void* p) {
    uint32_t a;
    asm("{ .reg .u64 t; cvta.to.shared.u64 t, %1; cvt.u32.u64 %0, t; }" : "=r"(a) : "l"(p));
    return a;
}
#define CP_ASYNC16(dst, src) \
    asm volatile("cp.async.cg.shared.global [%0], [%1], 16;" :: "r"(dst), "l"(src))
#define CP_COMMIT() asm volatile("cp.async.commit_group;" ::: "memory")
#define CP_WAIT1()  asm volatile("cp.async.wait_group 1;" ::: "memory")

#define LDMATRIX_X4(r0, r1, r2, r3, addr) \
    asm volatile("ldmatrix.sync.aligned.m8n8.x4.shared.b16 {%0,%1,%2,%3}, [%4];" \
                 : "=r"(r0), "=r"(r1), "=r"(r2), "=r"(r3) : "r"(addr))

__device__ __forceinline__ void mma_f16(float c[4],
                                        uint32_t a0, uint32_t a1, uint32_t a2, uint32_t a3,
                                        uint32_t b0, uint32_t b1) {
    asm volatile(
        "mma.sync.aligned.m16n8k16.row.col.f32.f16.f16.f32 "
        "{%0,%1,%2,%3}, {%4,%5,%6,%7}, {%8,%9}, {%0,%1,%2,%3};"
        : "+f"(c[0]), "+f"(c[1]), "+f"(c[2]), "+f"(c[3])
        : "r"(a0), "r"(a1), "r"(a2), "r"(a3), "r"(b0), "r"(b1));
}

__device__ __forceinline__ uint32_t h2bits(float x, float y) {
    __half2 h = __floats2half2_rn(x, y);
    return *(uint32_t*)&h;
}

// ---------------------------------------------------------------------------
// Kernel 1: row norms + labels + fp32 -> fp16 (16B stores) + g_done reset
// ---------------------------------------------------------------------------
__global__ void prep_kernel(const float* __restrict__ X, const int* __restrict__ tgt) {
    if (blockIdx.x == 0 && threadIdx.x == 0) g_done = 0;
    int warp = (blockIdx.x * blockDim.x + threadIdx.x) >> 5;
    int lane = threadIdx.x & 31;
    if (warp >= N) return;
    const float4* row = (const float4*)(X + (size_t)warp * D);   // 128 float4 per row
    uint4* hrow = (uint4*)(g_Xh + (size_t)warp * D);             // 64 uint4 per row
    float s = 0.f;
    #pragma unroll
    for (int i = 0; i < 2; i++) {
        const int c = lane + 32 * i;            // uint4 chunk 0..63
        float4 v0 = row[2 * c];
        float4 v1 = row[2 * c + 1];
        s += v0.x * v0.x + v0.y * v0.y + v0.z * v0.z + v0.w * v0.w;
        s += v1.x * v1.x + v1.y * v1.y + v1.z * v1.z + v1.w * v1.w;
        uint4 o;
        o.x = h2bits(v0.x, v0.y); o.y = h2bits(v0.z, v0.w);
        o.z = h2bits(v1.x, v1.y); o.w = h2bits(v1.z, v1.w);
        hrow[c] = o;
    }
    #pragma unroll
    for (int off = 16; off; off >>= 1) s += __shfl_down_sync(0xffffffffu, s, off);
    if (lane == 0) { g_sq[warp] = s; g_lbl[warp] = tgt[warp]; }
}

// ---------------------------------------------------------------------------
// Kernel 2: fp16 mma.sync gram-GEMM over the UPPER TRIANGLE of block-tiles,
// fused finalize in the last CTA. 512 thr, 4x4 warps, 32x32 warp tile,
// 3-stage cp.async pipeline, one syncthreads per k-tile, ldmatrix frags.
// ---------------------------------------------------------------------------
__global__ __launch_bounds__(512, 2)
void gemm_minmax_kernel(float* __restrict__ out) {
    extern __shared__ char smem[];
    const uint32_t sbase = smem_u32(smem);
    const int tid  = threadIdx.x;
    const int warp = tid >> 5, lane = tid & 31;
    const int wm = warp & 3, wn = warp >> 2;   // 4 x 4 warp grid
    const int g = lane >> 2, t = lane & 3;

    // decode linear block index -> (bi, bj) with bi <= bj
    int bi = 0, rem = blockIdx.x;
    while (rem >= NB - bi) { rem -= NB - bi; bi++; }
    const int bj = bi + rem;
    const bool diag = (bi == bj);
    const int i0 = bi * BM;
    const int j0 = bj * BN;

    float* s_jsq  = (float*)(smem + OFF_JSQ);
    int*   s_jlbl = (int*)(smem + OFF_JLBL);
    if (tid < 128) { s_jsq[tid] = g_sq[j0 + tid]; s_jlbl[tid] = g_lbl[j0 + tid]; }

    float c[2][4][4];
    #pragma unroll
    for (int mt = 0; mt < 2; mt++)
        #pragma unroll
        for (int nt = 0; nt < 4; nt++)
            #pragma unroll
            for (int q = 0; q < 4; q++) c[mt][nt][q] = 0.f;

    // ---- cp.async loader: 512 x 16B chunks per matrix, 1 per thread ----
    auto load_tile = [&](int kt) {
        const int s = kt % STAGES;
        const int k0 = kt * KC;
        const int row = tid >> 2;
        const int cc  = tid & 3;
        const uint32_t soff = (uint32_t)(row * (PADH * 2) + cc * 16);
        CP_ASYNC16(sbase + OFF_A(s) + soff, g_Xh + (size_t)(i0 + row) * D + k0 + cc * 8);
        if (!diag)
            CP_ASYNC16(sbase + OFF_B(s) + soff, g_Xh + (size_t)(j0 + row) * D + k0 + cc * 8);
        CP_COMMIT();
    };

    load_tile(0);
    load_tile(1);

    // ---- per-lane ldmatrix offsets (bytes within a tile) ----
    const uint32_t offA = (uint32_t)(((lane & 15) * PADH + (lane >> 4) * 8) * 2);
    const uint32_t offB = (uint32_t)((((lane & 7) + ((lane >> 4) & 1) * 8) * PADH
                                     + ((lane >> 3) & 1) * 8) * 2);
    const uint32_t aw = (uint32_t)(wm * 32) * PADH * 2u;
    const uint32_t bw = (uint32_t)(wn * 32) * PADH * 2u;

    uint32_t baseA[STAGES], baseB[STAGES];
    #pragma unroll
    for (int s = 0; s < STAGES; s++) {
        baseA[s] = sbase + OFF_A(s) + aw + offA;
        baseB[s] = (diag ? sbase + OFF_A(s) : sbase + OFF_B(s)) + bw + offB;
    }

    for (int kt = 0; kt < KT; kt++) {
        CP_WAIT1();
        __syncthreads();
        if (kt + 2 < KT) load_tile(kt + 2);
        else             CP_COMMIT();          // empty group keeps wait_group counting valid

        const int st = kt % STAGES;
        const uint32_t bA = baseA[st];
        const uint32_t bB = baseB[st];

        #pragma unroll
        for (int kk = 0; kk < 2; kk++) {       // k = 16 per mma
            const uint32_t ko = kk * 32;
            uint32_t a[2][4], b[4][2];
            #pragma unroll
            for (int mt = 0; mt < 2; mt++)
                LDMATRIX_X4(a[mt][0], a[mt][1], a[mt][2], a[mt][3],
                            bA + (uint32_t)(mt * 16) * PADH * 2u + ko);
            #pragma unroll
            for (int p = 0; p < 2; p++)
                LDMATRIX_X4(b[2 * p][0], b[2 * p][1], b[2 * p + 1][0], b[2 * p + 1][1],
                            bB + (uint32_t)(p * 16) * PADH * 2u + ko);
            #pragma unroll
            for (int mt = 0; mt < 2; mt++)
                #pragma unroll
                for (int nt = 0; nt < 4; nt++)
                    mma_f16(c[mt][nt], a[mt][0], a[mt][1], a[mt][2], a[mt][3],
                            b[nt][0], b[nt][1]);
        }
    }

    __syncthreads();   // all MMA smem reads done before epilogue

    // ---- epilogue: distances + row-fold + (off-diag) col-fold ----
    float* red_p = (float*)(smem + OFF_REDP);   // [128][4] across wn
    float* red_n = (float*)(smem + OFF_REDN);
    float* col_p = (float*)(smem + OFF_CP);     // [4][128] across wm
    float* col_n = (float*)(smem + OFF_CN);

    float cp[4][2], cn[4][2];
    #pragma unroll
    for (int nt = 0; nt < 4; nt++) { cp[nt][0] = cp[nt][1] = -FLT_MAX;
                                     cn[nt][0] = cn[nt][1] =  FLT_MAX; }

    #pragma unroll
    for (int mt = 0; mt < 2; mt++) {
        const int rlo = wm * 32 + mt * 16 + g;
        const int rhi = rlo + 8;
        const float isq_lo = g_sq[i0 + rlo], isq_hi = g_sq[i0 + rhi];
        const int   il_lo  = g_lbl[i0 + rlo], il_hi = g_lbl[i0 + rhi];
        float bpl = -FLT_MAX, bnl = FLT_MAX, bph = -FLT_MAX, bnh = FLT_MAX;
        #pragma unroll
        for (int nt = 0; nt < 4; nt++) {
            const int jc0 = wn * 32 + nt * 8 + 2 * t;
            const float jsq0 = s_jsq[jc0],  jsq1 = s_jsq[jc0 + 1];
            const int   jl0  = s_jlbl[jc0], jl1  = s_jlbl[jc0 + 1];
            float d;
            d = fmaf(-2.f, c[mt][nt][0], isq_lo + jsq0);
            if (il_lo == jl0) { bpl = fmaxf(bpl, d); cp[nt][0] = fmaxf(cp[nt][0], d); }
            else              { bnl = fminf(bnl, d); cn[nt][0] = fminf(cn[nt][0], d); }
            d = fmaf(-2.f, c[mt][nt][1], isq_lo + jsq1);
            if (il_lo == jl1) { bpl = fmaxf(bpl, d); cp[nt][1] = fmaxf(cp[nt][1], d); }
            else              { bnl = fminf(bnl, d); cn[nt][1] = fminf(cn[nt][1], d); }
            d = fmaf(-2.f, c[mt][nt][2], isq_hi + jsq0);
            if (il_hi == jl0) { bph = fmaxf(bph, d); cp[nt][0] = fmaxf(cp[nt][0], d); }
            else              { bnh = fminf(bnh, d); cn[nt][0] = fminf(cn[nt][0], d); }
            d = fmaf(-2.f, c[mt][nt][3], isq_hi + jsq1);
            if (il_hi == jl1) { bph = fmaxf(bph, d); cp[nt][1] = fmaxf(cp[nt][1], d); }
            else              { bnh = fminf(bnh, d); cn[nt][1] = fminf(cn[nt][1], d); }
        }
        bpl = fmaxf(bpl, __shfl_down_sync(0xffffffffu, bpl, 2));
        bpl = fmaxf(bpl, __shfl_down_sync(0xffffffffu, bpl, 1));
        bnl = fminf(bnl, __shfl_down_sync(0xffffffffu, bnl, 2));
        bnl = fminf(bnl, __shfl_down_sync(0xffffffffu, bnl, 1));
        bph = fmaxf(bph, __shfl_down_sync(0xffffffffu, bph, 2));
        bph = fmaxf(bph, __shfl_down_sync(0xffffffffu, bph, 1));
        bnh = fminf(bnh, __shfl_down_sync(0xffffffffu, bnh, 2));
        bnh = fminf(bnh, __shfl_down_sync(0xffffffffu, bnh, 1));
        if (t == 0) {
            red_p[rlo * 4 + wn] = bpl; red_n[rlo * 4 + wn] = bnl;
            red_p[rhi * 4 + wn] = bph; red_n[rhi * 4 + wn] = bnh;
        }
    }

    if (!diag) {
        #pragma unroll
        for (int nt = 0; nt < 4; nt++) {
            #pragma unroll
            for (int q = 0; q < 2; q++) {
                float p = cp[nt][q], n = cn[nt][q];
                #pragma unroll
                for (int off = 4; off <= 16; off <<= 1) {
                    p = fmaxf(p, __shfl_xor_sync(0xffffffffu, p, off));
                    n = fminf(n, __shfl_xor_sync(0xffffffffu, n, off));
                }
                if (lane < 4) {
                    const int col = wn * 32 + nt * 8 + 2 * t + q;
                    col_p[wm * 128 + col] = p;
                    col_n[wm * 128 + col] = n;
                }
            }
        }
    }
    __syncthreads();

    if (tid < 128) {
        float p = red_p[tid * 4 + 0], n = red_n[tid * 4 + 0];
        #pragma unroll
        for (int w = 1; w < 4; w++) {
            p = fmaxf(p, red_p[tid * 4 + w]);
            n = fminf(n, red_n[tid * 4 + w]);
        }
        g_pos[bj * N + i0 + tid] = p;
        g_neg[bj * N + i0 + tid] = n;

        if (!diag) {
            float pc = col_p[tid], nc = col_n[tid];
            #pragma unroll
            for (int w = 1; w < 4; w++) {
                pc = fmaxf(pc, col_p[w * 128 + tid]);
                nc = fminf(nc, col_n[w * 128 + tid]);
            }
            g_pos[bi * N + j0 + tid] = pc;
            g_neg[bi * N + j0 + tid] = nc;
        }
    }

    // ---- fused finalize: last CTA folds all partials -> loss ----
    __threadfence();
    __syncthreads();
    __shared__ unsigned s_rank;
    if (tid == 0) s_rank = atomicAdd(&g_done, 1u);
    __syncthreads();
    if (s_rank == NTILES - 1) {
        __threadfence();
        float* red = (float*)(smem + OFF_REDP);   // 512 floats
        float s = 0.f;
        for (int i = tid; i < N; i += 512) {
            float p = -FLT_MAX, n = FLT_MAX;
            #pragma unroll
            for (int sp = 0; sp < NJT; sp++) {
                p = fmaxf(p, g_pos[sp * N + i]);
                n = fminf(n, g_neg[sp * N + i]);
            }
            const float v = p - n + MARGIN;
            s += (v > 0.f) ? v : 0.f;
        }
        red[tid] = s;
        __syncthreads();
        #pragma unroll
        for (int off = 256; off; off >>= 1) {
            if (tid < off) red[tid] += red[tid + off];
            __syncthreads();
        }
        if (tid == 0) out[0] = red[0] / (float)N;
    }
}

// ---------------------------------------------------------------------------
extern "C" void kernel_launch(void* const* d_in, const int* in_sizes, int n_in,
                              void* d_out, int out_size) {
    const float* X   = (const float*)d_in[0];
    const int*   tgt = (const int*)d_in[1];
    float*       out = (float*)d_out;

    cudaFuncSetAttribute(gemm_minmax_kernel,
                         cudaFuncAttributeMaxDynamicSharedMemorySize, SMEM_TOTAL);

    prep_kernel<<<N / 8, 256>>>(X, tgt);
    gemm_minmax_kernel<<<NTILES, 512, SMEM_TOTAL>>>(out);
}

// round 16
// speedup vs baseline: 1.0863x; 1.0863x over previous
#include <cuda_runtime.h>
#include <cuda_fp16.h>
#include <cstdint>
#include <float.h>

// ---------------------------------------------------------------------------
// Problem constants
// ---------------------------------------------------------------------------
#define N 4096
#define D 512
#define MARGIN 200.0f

// Tiling: CTA tile 128x128, 8 warps in 2(m) x 4(n), warp tile 64x32 (R12 shape)
#define BM 128
#define BN 128
#define KC 32                 // k per smem stage (32 halfs = 64B per row)
#define KT (D / KC)           // 16 k-tiles
#define STAGES 3
#define NB (N / BM)           // 32 blocks per dim
#define NJT NB
#define NTILES (NB * (NB + 1) / 2)          // 528 upper-triangle tiles

#define TILE_B 8192                         // one 128x32-half blocked tile (bytes)
#define OFF_A(s)  ((s) * TILE_B)                      // 0, 8192, 16384
#define OFF_B(s)  (STAGES * TILE_B + (s) * TILE_B)    // 24576 ...
#define OFF_REDP  (2 * STAGES * TILE_B)               // 49152: [128][4] floats
#define OFF_REDN  (OFF_REDP + 2048)
#define OFF_CP    (OFF_REDN + 2048)                   // [2][128] floats
#define OFF_CN    (OFF_CP + 1024)
#define OFF_JSQ   (OFF_CN + 1024)
#define OFF_JLBL  (OFF_JSQ + 512)
#define OFF_MBAR  (OFF_JLBL + 512)                    // 3 x 8B mbarriers
#define SMEM_TOTAL (OFF_MBAR + 64)                    // 56384 B -> 2 CTAs/SM

// ---------------------------------------------------------------------------
// Device scratch (static module storage; no runtime allocation)
// g_Xh layout: blocked tiles [rowblock 0..31][ktile 0..15][8KB swizzled tile]
// tile inner: row r (0..127) x 64B, byte off = r*64 + kb, stored at
//   (r*64) + (kb ^ (((r>>1)&3)<<4))   -> ldmatrix conflict-free
// ---------------------------------------------------------------------------
__device__ __half    g_Xh[N * D];   // 4 MB
__device__ float     g_sq[N];
__device__ int       g_lbl[N];
__device__ float     g_pos[NJT * N];
__device__ float     g_neg[NJT * N];
__device__ unsigned  g_done;

// ---------------------------------------------------------------------------
// PTX helpers (sm_90 baseline or older — compiles for plain sm_100 target)
// ---------------------------------------------------------------------------
__device__ __forceinline__ uint32_t smem_u32(const void* p) {
    uint32_t a;
    asm("{ .reg .u64 t; cvta.to.shared.u64 t, %1; cvt.u32.u64 %0, t; }" : "=r"(a) : "l"(p));
    return a;
}
#define MBARRIER_INIT(addr, cnt) \
    asm volatile("mbarrier.init.shared.b64 [%0], %1;" :: "r"((uint32_t)(addr)), "r"((uint32_t)(cnt)) : "memory")
#define MBARRIER_EXPECT_TX(addr, bytes) \
    asm volatile("mbarrier.arrive.expect_tx.shared.b64 _, [%0], %1;" \
                 :: "r"((uint32_t)(addr)), "r"((uint32_t)(bytes)) : "memory")
#define MBARRIER_WAIT_PARITY(addr, parity) do {                                   \
    uint32_t _m = (uint32_t)(addr); uint32_t _p = (uint32_t)(parity);             \
    asm volatile(                                                                 \
        "{\n\t.reg .pred P1;\n\t"                                                 \
        "WAIT_LOOP_%=:\n\t"                                                       \
        "mbarrier.try_wait.parity.shared.b64 P1, [%0], %1;\n\t"                   \
        "@P1 bra.uni WAIT_DONE_%=;\n\t"                                           \
        "bra.uni WAIT_LOOP_%=;\n\t"                                               \
        "WAIT_DONE_%=:\n\t}"                                                      \
        :: "r"(_m), "r"(_p) : "memory");                                          \
} while (0)
#define BULK_CP(dst_smem, src_gmem, bytes, mbar) \
    asm volatile("cp.async.bulk.shared::cta.global.mbarrier::complete_tx::bytes " \
                 "[%0], [%1], %2, [%3];" \
                 :: "r"((uint32_t)(dst_smem)), "l"(src_gmem), "r"((uint32_t)(bytes)), \
                    "r"((uint32_t)(mbar)) : "memory")

#define LDMATRIX_X4(r0, r1, r2, r3, addr) \
    asm volatile("ldmatrix.sync.aligned.m8n8.x4.shared.b16 {%0,%1,%2,%3}, [%4];" \
                 : "=r"(r0), "=r"(r1), "=r"(r2), "=r"(r3) : "r"(addr))

__device__ __forceinline__ void mma_f16(float c[4],
                                        uint32_t a0, uint32_t a1, uint32_t a2, uint32_t a3,
                                        uint32_t b0, uint32_t b1) {
    asm volatile(
        "mma.sync.aligned.m16n8k16.row.col.f32.f16.f16.f32 "
        "{%0,%1,%2,%3}, {%4,%5,%6,%7}, {%8,%9}, {%0,%1,%2,%3};"
        : "+f"(c[0]), "+f"(c[1]), "+f"(c[2]), "+f"(c[3])
        : "r"(a0), "r"(a1), "r"(a2), "r"(a3), "r"(b0), "r"(b1));
}

__device__ __forceinline__ uint32_t h2bits(float x, float y) {
    __half2 h = __floats2half2_rn(x, y);
    return *(uint32_t*)&h;
}

// ---------------------------------------------------------------------------
// Kernel 1: row norms + labels + fp32 -> fp16 into BLOCKED SWIZZLED tiles
// ---------------------------------------------------------------------------
__global__ void prep_kernel(const float* __restrict__ X, const int* __restrict__ tgt) {
    if (blockIdx.x == 0 && threadIdx.x == 0) g_done = 0;
    int i = (blockIdx.x * blockDim.x + threadIdx.x) >> 5;   // row
    int lane = threadIdx.x & 31;
    if (i >= N) return;
    const float4* row4 = (const float4*)(X + (size_t)i * D);   // 128 float4
    const int r = i & 127;
    const uint32_t key = (uint32_t)(((r >> 1) & 3) << 4);
    char* blk = (char*)g_Xh + (size_t)(i >> 7) * (16 * TILE_B);
    float s = 0.f;
    #pragma unroll
    for (int it = 0; it < 2; it++) {
        const int cg = lane + 32 * it;          // 16B chunk 0..63
        const int kt = cg >> 2;
        const int cc = cg & 3;
        float4 v0 = row4[2 * cg];
        float4 v1 = row4[2 * cg + 1];
        s += v0.x * v0.x + v0.y * v0.y + v0.z * v0.z + v0.w * v0.w;
        s += v1.x * v1.x + v1.y * v1.y + v1.z * v1.z + v1.w * v1.w;
        uint4 o;
        o.x = h2bits(v0.x, v0.y); o.y = h2bits(v0.z, v0.w);
        o.z = h2bits(v1.x, v1.y); o.w = h2bits(v1.z, v1.w);
        const uint32_t inner = (uint32_t)(r * 64) + (((uint32_t)(cc * 16)) ^ key);
        *(uint4*)(blk + (size_t)kt * TILE_B + inner) = o;
    }
    #pragma unroll
    for (int off = 16; off; off >>= 1) s += __shfl_down_sync(0xffffffffu, s, off);
    if (lane == 0) { g_sq[i] = s; g_lbl[i] = tgt[i]; }
}

// ---------------------------------------------------------------------------
// Kernel 2: fp16 mma.sync gram-GEMM (upper triangle), cp.async.bulk staging,
// fused finalize in the last CTA. 256 thr, 2x4 warps, 64x32 warp tile.
// ---------------------------------------------------------------------------
__global__ __launch_bounds__(256, 2)
void gemm_minmax_kernel(float* __restrict__ out) {
    extern __shared__ char smem[];
    const uint32_t sbase = smem_u32(smem);
    const int tid  = threadIdx.x;
    const int warp = tid >> 5, lane = tid & 31;
    const int wm = warp & 1, wn = warp >> 1;   // 2 x 4 warp grid
    const int g = lane >> 2, t = lane & 3;

    // decode linear block index -> (bi, bj) with bi <= bj
    int bi = 0, rem = blockIdx.x;
    while (rem >= NB - bi) { rem -= NB - bi; bi++; }
    const int bj = bi + rem;
    const bool diag = (bi == bj);
    const int i0 = bi * BM;
    const int j0 = bj * BN;

    float* s_jsq  = (float*)(smem + OFF_JSQ);
    int*   s_jlbl = (int*)(smem + OFF_JLBL);
    if (tid < 128) { s_jsq[tid] = g_sq[j0 + tid]; s_jlbl[tid] = g_lbl[j0 + tid]; }

    if (tid == 0) {
        #pragma unroll
        for (int s = 0; s < STAGES; s++) MBARRIER_INIT(sbase + OFF_MBAR + s * 8, 1);
    }

    float c[4][4][4];
    #pragma unroll
    for (int mt = 0; mt < 4; mt++)
        #pragma unroll
        for (int nt = 0; nt < 4; nt++)
            #pragma unroll
            for (int q = 0; q < 4; q++) c[mt][nt][q] = 0.f;

    __syncthreads();   // mbarriers initialized before any expect_tx/wait

    // ---- bulk loader: 1 (diag) or 2 x 8KB per k-tile, single thread ----
    auto issue_load = [&](int kt) {
        const int s = kt % STAGES;
        const uint32_t mbar = sbase + OFF_MBAR + s * 8;
        MBARRIER_EXPECT_TX(mbar, diag ? TILE_B : 2 * TILE_B);
        const char* srcA = (const char*)g_Xh + ((size_t)(bi * 16 + kt)) * TILE_B;
        BULK_CP(sbase + OFF_A(s), srcA, TILE_B, mbar);
        if (!diag) {
            const char* srcB = (const char*)g_Xh + ((size_t)(bj * 16 + kt)) * TILE_B;
            BULK_CP(sbase + OFF_B(s), srcB, TILE_B, mbar);
        }
    };
    if (tid == 0) { issue_load(0); issue_load(1); }

    // ---- per-lane ldmatrix swizzled addressing ----
    // A: row = wm*64 + mt*16 + (lane&15); kbyte = kk*32 + (lane>>4)*16
    // B: row = wn*32 + p*16 + (lane&7) + ((lane>>4)&1)*8; kbyte = kk*32 + ((lane>>3)&1)*16
    // smem byte = row*64 + (kbyte ^ (((row>>1)&3)<<4))
    const int rA = lane & 15;
    const uint32_t kAl = (uint32_t)((lane >> 4) * 16);
    uint32_t aoff[4], akey[4];
    #pragma unroll
    for (int mt = 0; mt < 4; mt++) {
        const int row = wm * 64 + mt * 16 + rA;
        aoff[mt] = (uint32_t)(row * 64);
        akey[mt] = (uint32_t)(((row >> 1) & 3) << 4);
    }
    const int rB = (lane & 7) + ((lane >> 4) & 1) * 8;
    const uint32_t kBl = (uint32_t)(((lane >> 3) & 1) * 16);
    uint32_t boff[2], bkey[2];
    #pragma unroll
    for (int p = 0; p < 2; p++) {
        const int row = wn * 32 + p * 16 + rB;
        boff[p] = (uint32_t)(row * 64);
        bkey[p] = (uint32_t)(((row >> 1) & 3) << 4);
    }

    for (int kt = 0; kt < KT; kt++) {
        MBARRIER_WAIT_PARITY(sbase + OFF_MBAR + (kt % STAGES) * 8, (kt / STAGES) & 1);
        __syncthreads();   // all LDSM of kt-1 done before slot reuse
        if (tid == 0 && kt + 2 < KT) issue_load(kt + 2);

        const int st = kt % STAGES;
        const uint32_t bA = sbase + OFF_A(st);
        const uint32_t bB = diag ? bA : sbase + OFF_B(st);

        #pragma unroll
        for (int kk = 0; kk < 2; kk++) {       // k = 16 per mma
            const uint32_t koA = (uint32_t)(kk * 32) + kAl;
            const uint32_t koB = (uint32_t)(kk * 32) + kBl;
            uint32_t a[4][4], b[4][2];
            #pragma unroll
            for (int mt = 0; mt < 4; mt++)
                LDMATRIX_X4(a[mt][0], a[mt][1], a[mt][2], a[mt][3],
                            bA + aoff[mt] + (koA ^ akey[mt]));
            #pragma unroll
            for (int p = 0; p < 2; p++)
                LDMATRIX_X4(b[2 * p][0], b[2 * p][1], b[2 * p + 1][0], b[2 * p + 1][1],
                            bB + boff[p] + (koB ^ bkey[p]));
            #pragma unroll
            for (int mt = 0; mt < 4; mt++)
                #pragma unroll
                for (int nt = 0; nt < 4; nt++)
                    mma_f16(c[mt][nt], a[mt][0], a[mt][1], a[mt][2], a[mt][3],
                            b[nt][0], b[nt][1]);
        }
    }

    __syncthreads();   // all MMA smem reads done before epilogue reuses smem

    // ---- epilogue: distances + row-fold + (off-diag) col-fold ----
    float* red_p = (float*)(smem + OFF_REDP);
    float* red_n = (float*)(smem + OFF_REDN);
    float* col_p = (float*)(smem + OFF_CP);
    float* col_n = (float*)(smem + OFF_CN);

    float cp[4][2], cn[4][2];
    #pragma unroll
    for (int nt = 0; nt < 4; nt++) { cp[nt][0] = cp[nt][1] = -FLT_MAX;
                                     cn[nt][0] = cn[nt][1] =  FLT_MAX; }

    #pragma unroll
    for (int mt = 0; mt < 4; mt++) {
        const int rlo = wm * 64 + mt * 16 + g;
        const int rhi = rlo + 8;
        const float isq_lo = g_sq[i0 + rlo], isq_hi = g_sq[i0 + rhi];
        const int   il_lo  = g_lbl[i0 + rlo], il_hi = g_lbl[i0 + rhi];
        float bpl = -FLT_MAX, bnl = FLT_MAX, bph = -FLT_MAX, bnh = FLT_MAX;
        #pragma unroll
        for (int nt = 0; nt < 4; nt++) {
            const int jc0 = wn * 32 + nt * 8 + 2 * t;
            const float jsq0 = s_jsq[jc0],  jsq1 = s_jsq[jc0 + 1];
            const int   jl0  = s_jlbl[jc0], jl1  = s_jlbl[jc0 + 1];
            float d;
            d = fmaf(-2.f, c[mt][nt][0], isq_lo + jsq0);
            if (il_lo == jl0) { bpl = fmaxf(bpl, d); cp[nt][0] = fmaxf(cp[nt][0], d); }
            else              { bnl = fminf(bnl, d); cn[nt][0] = fminf(cn[nt][0], d); }
            d = fmaf(-2.f, c[mt][nt][1], isq_lo + jsq1);
            if (il_lo == jl1) { bpl = fmaxf(bpl, d); cp[nt][1] = fmaxf(cp[nt][1], d); }
            else              { bnl = fminf(bnl, d); cn[nt][1] = fminf(cn[nt][1], d); }
            d = fmaf(-2.f, c[mt][nt][2], isq_hi + jsq0);
            if (il_hi == jl0) { bph = fmaxf(bph, d); cp[nt][0] = fmaxf(cp[nt][0], d); }
            else              { bnh = fminf(bnh, d); cn[nt][0] = fminf(cn[nt][0], d); }
            d = fmaf(-2.f, c[mt][nt][3], isq_hi + jsq1);
            if (il_hi == jl1) { bph = fmaxf(bph, d); cp[nt][1] = fmaxf(cp[nt][1], d); }
            else              { bnh = fminf(bnh, d); cn[nt][1] = fminf(cn[nt][1], d); }
        }
        bpl = fmaxf(bpl, __shfl_down_sync(0xffffffffu, bpl, 2));
        bpl = fmaxf(bpl, __shfl_down_sync(0xffffffffu, bpl, 1));
        bnl = fminf(bnl, __shfl_down_sync(0xffffffffu, bnl, 2));
        bnl = fminf(bnl, __shfl_down_sync(0xffffffffu, bnl, 1));
        bph = fmaxf(bph, __shfl_down_sync(0xffffffffu, bph, 2));
        bph = fmaxf(bph, __shfl_down_sync(0xffffffffu, bph, 1));
        bnh = fminf(bnh, __shfl_down_sync(0xffffffffu, bnh, 2));
        bnh = fminf(bnh, __shfl_down_sync(0xffffffffu, bnh, 1));
        if (t == 0) {
            red_p[rlo * 4 + wn] = bpl; red_n[rlo * 4 + wn] = bnl;
            red_p[rhi * 4 + wn] = bph; red_n[rhi * 4 + wn] = bnh;
        }
    }

    if (!diag) {
        #pragma unroll
        for (int nt = 0; nt < 4; nt++) {
            #pragma unroll
            for (int q = 0; q < 2; q++) {
                float p = cp[nt][q], n = cn[nt][q];
                #pragma unroll
                for (int off = 4; off <= 16; off <<= 1) {
                    p = fmaxf(p, __shfl_xor_sync(0xffffffffu, p, off));
                    n = fminf(n, __shfl_xor_sync(0xffffffffu, n, off));
                }
                if (lane < 4) {
                    const int col = wn * 32 + nt * 8 + 2 * t + q;
                    col_p[wm * 128 + col] = p;
                    col_n[wm * 128 + col] = n;
                }
            }
        }
    }
    __syncthreads();

    if (tid < 128) {
        float p = red_p[tid * 4 + 0], n = red_n[tid * 4 + 0];
        #pragma unroll
        for (int w = 1; w < 4; w++) {
            p = fmaxf(p, red_p[tid * 4 + w]);
            n = fminf(n, red_n[tid * 4 + w]);
        }
        g_pos[bj * N + i0 + tid] = p;
        g_neg[bj * N + i0 + tid] = n;

        if (!diag) {
            float pc = fmaxf(col_p[tid], col_p[128 + tid]);
            float nc = fminf(col_n[tid], col_n[128 + tid]);
            g_pos[bi * N + j0 + tid] = pc;
            g_neg[bi * N + j0 + tid] = nc;
        }
    }

    // ---- fused finalize: last CTA folds all partials -> loss ----
    __threadfence();
    __syncthreads();
    __shared__ unsigned s_rank;
    if (tid == 0) s_rank = atomicAdd(&g_done, 1u);
    __syncthreads();
    if (s_rank == NTILES - 1) {
        __threadfence();
        float* red = (float*)(smem + OFF_REDP);
        float s = 0.f;
        for (int i = tid; i < N; i += 256) {
            float p = -FLT_MAX, n = FLT_MAX;
            #pragma unroll
            for (int sp = 0; sp < NJT; sp++) {
                p = fmaxf(p, g_pos[sp * N + i]);
                n = fminf(n, g_neg[sp * N + i]);
            }
            const float v = p - n + MARGIN;
            s += (v > 0.f) ? v : 0.f;
        }
        red[tid] = s;
        __syncthreads();
        #pragma unroll
        for (int off = 128; off; off >>= 1) {
            if (tid < off) red[tid] += red[tid + off];
            __syncthreads();
        }
        if (tid == 0) out[0] = red[0] / (float)N;
    }
}

// ---------------------------------------------------------------------------
extern "C" void kernel_launch(void* const* d_in, const int* in_sizes, int n_in,
                              void* d_out, int out_size) {
    const float* X   = (const float*)d_in[0];
    const int*   tgt = (const int*)d_in[1];
    float*       out = (float*)d_out;

    cudaFuncSetAttribute(gemm_minmax_kernel,
                         cudaFuncAttributeMaxDynamicSharedMemorySize, SMEM_TOTAL);

    prep_kernel<<<N / 8, 256>>>(X, tgt);
    gemm_minmax_kernel<<<NTILES, 256, SMEM_TOTAL>>>(out);
}